// round 11
// baseline (speedup 1.0000x reference)
#include <cuda_runtime.h>
#include <cuda_fp16.h>
#include <math.h>
#include <stdint.h>

#define Bb 4
#define Tt 1024
#define Vv 50257
#define Ee 1024
#define Hh 16
#define Ll 8
#define Dd 64
#define BT (Bb*Tt)
#define NPAD 50432   // Vv padded to multiple of 256
#define QS  (3*Ee)   // packed qkv row stride

// ---------------- device scratch (static, allocation-free) ----------------
__device__ float  g_x [BT*Ee];                       // fp32 residual stream
__device__ __half g_hh[BT*Ee];                       // LN output (GEMM A)
__device__ __half g_qkvh[(size_t)BT * QS];           // packed q|k|v half
__device__ __half g_oh[BT*Ee];
__device__ __half g_ffh[BT*Ee];
__device__ __half g_wt[(size_t)3 * Ll * Ee * Ee];    // proj/fw1/fw2 transposed [N][K] half
__device__ __half g_wqkv[(size_t)Ll * 3 * Ee * Ee];  // per-layer [3E][E] transposed half
__device__ __half g_lmwt[(size_t)NPAD * Ee];         // LM head transposed [NPAD][Ee] half
__device__ float  g_rowloss[BT];
__device__ float  g_logits_scratch[205852672ull];    // fallback logits buffer

// ---------------- helpers ----------------
__device__ __forceinline__ void mma16(float* c, const uint32_t* a, const uint32_t* b){
  asm volatile("mma.sync.aligned.m16n8k16.row.col.f32.f16.f16.f32 "
    "{%0,%1,%2,%3}, {%4,%5,%6,%7}, {%8,%9}, {%0,%1,%2,%3};"
    : "+f"(c[0]), "+f"(c[1]), "+f"(c[2]), "+f"(c[3])
    : "r"(a[0]), "r"(a[1]), "r"(a[2]), "r"(a[3]), "r"(b[0]), "r"(b[1]));
}
__device__ __forceinline__ void ldsm_x4(uint32_t& r0, uint32_t& r1,
                                        uint32_t& r2, uint32_t& r3, uint32_t addr){
  asm volatile("ldmatrix.sync.aligned.m8n8.x4.shared.b16 {%0,%1,%2,%3}, [%4];"
    : "=r"(r0), "=r"(r1), "=r"(r2), "=r"(r3) : "r"(addr));
}
__device__ __forceinline__ void ldsm_x4_t(uint32_t& r0, uint32_t& r1,
                                          uint32_t& r2, uint32_t& r3, uint32_t addr){
  asm volatile("ldmatrix.sync.aligned.m8n8.x4.trans.shared.b16 {%0,%1,%2,%3}, [%4];"
    : "=r"(r0), "=r"(r1), "=r"(r2), "=r"(r3) : "r"(addr));
}
__device__ __forceinline__ void cp16(void* smem_ptr, const void* g){
  uint32_t s = (uint32_t)__cvta_generic_to_shared(smem_ptr);
  asm volatile("cp.async.cg.shared.global [%0], [%1], 16;" :: "r"(s), "l"(g));
}
__device__ __forceinline__ void cp_commit(){ asm volatile("cp.async.commit_group;"); }
template<int N> __device__ __forceinline__ void cp_wait(){
  asm volatile("cp.async.wait_group %0;" :: "n"(N));
}
__device__ __forceinline__ uint32_t smem_u32(const void* p){
  return (uint32_t)__cvta_generic_to_shared(p);
}

__device__ __forceinline__ float warpSum(float v){
  #pragma unroll
  for (int o = 16; o > 0; o >>= 1) v += __shfl_down_sync(0xffffffffu, v, o);
  return v;
}
__device__ __forceinline__ float warpMax(float v){
  #pragma unroll
  for (int o = 16; o > 0; o >>= 1) v = fmaxf(v, __shfl_down_sync(0xffffffffu, v, o));
  return v;
}
template<int OP>
__device__ __forceinline__ float blockReduce(float v){
  __shared__ float sh[33];
  int lane = threadIdx.x & 31, wid = threadIdx.x >> 5;
  v = OP ? warpMax(v) : warpSum(v);
  __syncthreads();
  if (lane == 0) sh[wid] = v;
  __syncthreads();
  int nw = blockDim.x >> 5;
  if (wid == 0){
    float u = (lane < nw) ? sh[lane] : (OP ? -INFINITY : 0.0f);
    u = OP ? warpMax(u) : warpSum(u);
    if (lane == 0) sh[32] = u;
  }
  __syncthreads();
  return sh[32];
}

// ---------------- embedding (fp32 residual) ----------------
__global__ void embed_kernel(const int* __restrict__ idx,
                             const float* __restrict__ tok,
                             const float* __restrict__ pos){
  int i  = blockIdx.x * 256 + threadIdx.x;
  int e4 = i & (Ee/4 - 1);
  int bt = i >> 8;
  int t  = bt & (Tt - 1);
  int token = idx[bt];
  float4 tv = ((const float4*)(tok + (size_t)token * Ee))[e4];
  float4 pv = ((const float4*)(pos + (size_t)t     * Ee))[e4];
  ((float4*)(g_x + (size_t)bt * Ee))[e4] =
      make_float4(tv.x*pv.x, tv.y*pv.y, tv.z*pv.z, tv.w*pv.w);
}

// ---------------- layernorm: fp32 in -> half out ----------------
__global__ void ln_kernel(const float* __restrict__ in, __half* __restrict__ out,
                          const float* __restrict__ w, const float* __restrict__ b){
  int row = blockIdx.x;
  float4 v = ((const float4*)(in + (size_t)row * Ee))[threadIdx.x];
  float mu = blockReduce<0>(v.x + v.y + v.z + v.w) * (1.0f / Ee);
  float dx = v.x - mu, dy = v.y - mu, dz = v.z - mu, dw = v.w - mu;
  float var = blockReduce<0>(dx*dx + dy*dy + dz*dz + dw*dw) * (1.0f / Ee);
  float rs = rsqrtf(var + 1e-5f);
  float4 wv = ((const float4*)w)[threadIdx.x];
  float4 bv = ((const float4*)b)[threadIdx.x];
  __half2* op = (__half2*)(out + (size_t)row * Ee) + threadIdx.x * 2;
  op[0] = __floats2half2_rn(dx*rs*wv.x + bv.x, dy*rs*wv.y + bv.y);
  op[1] = __floats2half2_rn(dz*rs*wv.z + bv.z, dw*rs*wv.w + bv.w);
}

// ---------------- weight transpose+half: src[K][N] f32 (per layer EE) -> dst[N][K] half
__global__ void transpose_w(const float* __restrict__ src, __half* __restrict__ dst,
                            size_t dstLayerStride){
  __shared__ float t[32][33];
  size_t sbase = (size_t)blockIdx.z * Ee * Ee;
  size_t dbase = (size_t)blockIdx.z * dstLayerStride;
  int k0 = blockIdx.x * 32, n0 = blockIdx.y * 32;
  int tx = threadIdx.x, ty = threadIdx.y;  // 32 x 8
  #pragma unroll
  for (int i = 0; i < 4; i++)
    t[ty + i*8][tx] = src[sbase + (size_t)(k0 + ty + i*8) * Ee + n0 + tx];
  __syncthreads();
  #pragma unroll
  for (int i = 0; i < 4; i++)
    dst[dbase + (size_t)(n0 + ty + i*8) * Ee + k0 + tx] = __float2half(t[tx][ty + i*8]);
}

// LM head: src[Ee][Vv] f32 -> dst[NPAD][Ee] half (zero-padded rows)
__global__ void transpose_lm(const float* __restrict__ src, __half* __restrict__ dst){
  __shared__ float t[32][33];
  int k0 = blockIdx.x * 32, n0 = blockIdx.y * 32;
  int tx = threadIdx.x, ty = threadIdx.y;
  #pragma unroll
  for (int i = 0; i < 4; i++){
    int n = n0 + tx;
    t[ty + i*8][tx] = (n < Vv) ? src[(size_t)(k0 + ty + i*8) * Vv + n] : 0.0f;
  }
  __syncthreads();
  #pragma unroll
  for (int i = 0; i < 4; i++)
    dst[(size_t)(n0 + ty + i*8) * Ee + k0 + tx] = __float2half(t[tx][ty + i*8]);
}

// ---------------- fp16 tensor-core GEMM: BM=128, BN=256, BK=64, warp tile 64x64 ----
// C[M,N] = act(A[M,K]@Bt[N,K]^T + bias)(+resid). 8 warps (2m x 4n), mma m16n8k16.
#define HPITCH 72                        // halfs per smem row (36 words; conflict-free)
#define TILEA  (128*HPITCH)              // 9216 halfs
#define TILEB  (256*HPITCH)              // 18432 halfs
#define STAGEH (TILEA + TILEB)           // 27648 halfs per stage
#define SGEMM_SMEM (2*STAGEH*2)          // 110592 bytes (2 stages)

template<bool RELU, bool RESID, bool OUTH>
__global__ __launch_bounds__(256, 1)
void sgemm_hc(const __half* __restrict__ A, const __half* __restrict__ Bt,
              const float* __restrict__ bias, const float* __restrict__ resid,
              void* __restrict__ C, int M, int N, int K, int Kb){
  extern __shared__ __align__(16) __half hsm[];
  int tid = threadIdx.x;
  int lane = tid & 31, warp = tid >> 5;
  int wm = warp >> 2, wn = warp & 3;
  int qk = lane & 3, qm = lane >> 2;
  int row0 = blockIdx.x * 128, col0 = blockIdx.y * 256;
  float acc[4][8][4] = {};

  // per-lane ldmatrix offsets (half units)
  int j8 = lane >> 3, r8 = lane & 7;
  int a_off[4], b_off[4];
  #pragma unroll
  for (int mi = 0; mi < 4; mi++)
    a_off[mi] = (wm*64 + mi*16 + ((j8 & 1) << 3) + r8) * HPITCH + ((j8 >> 1) << 3);
  #pragma unroll
  for (int p = 0; p < 4; p++)
    b_off[p] = (wn*64 + (p*2 + (j8 >> 1))*8 + r8) * HPITCH + ((j8 & 1) << 3);

  auto prefetch = [&](int kt, int s){
    __half* As = hsm + s * STAGEH;
    __half* Bs = As + TILEA;
    #pragma unroll
    for (int l = 0; l < 4; l++){
      int f = tid + l * 256;                 // 1024 chunks: 128 rows x 8 x 16B
      int r = f >> 3, c8 = (f & 7) << 3;
      cp16(As + r * HPITCH + c8, A  + (size_t)(row0 + r) * K  + kt + c8);
    }
    #pragma unroll
    for (int l = 0; l < 8; l++){
      int f = tid + l * 256;                 // 2048 chunks: 256 rows x 8 x 16B
      int r = f >> 3, c8 = (f & 7) << 3;
      cp16(Bs + r * HPITCH + c8, Bt + (size_t)(col0 + r) * Kb + kt + c8);
    }
  };

  int nk = K >> 6;                            // 64-half K chunks
  prefetch(0, 0); cp_commit();

  for (int t = 0; t < nk; t++){
    cp_wait<0>();
    __syncthreads();     // publishes stage t&1; orders prior reads of (t+1)&1 vs prefetch
    if (t + 1 < nk){ prefetch((t + 1) << 6, (t + 1) & 1); cp_commit(); }
    uint32_t aU = smem_u32(hsm + (t & 1) * STAGEH);
    uint32_t bU = aU + TILEA * 2;
    #pragma unroll
    for (int ks = 0; ks < 4; ks++){
      int k0 = ks * 16;
      uint32_t af[4][4], bf[8][2];
      #pragma unroll
      for (int mi = 0; mi < 4; mi++)
        ldsm_x4(af[mi][0], af[mi][1], af[mi][2], af[mi][3],
                aU + (uint32_t)(a_off[mi] + k0) * 2);
      #pragma unroll
      for (int p = 0; p < 4; p++)
        ldsm_x4(bf[p*2][0], bf[p*2][1], bf[p*2+1][0], bf[p*2+1][1],
                bU + (uint32_t)(b_off[p] + k0) * 2);
      #pragma unroll
      for (int mi = 0; mi < 4; mi++)
        #pragma unroll
        for (int ni = 0; ni < 8; ni++)
          mma16(acc[mi][ni], af[mi], bf[ni]);
    }
  }

  #pragma unroll
  for (int mi = 0; mi < 4; mi++){
    int r = row0 + wm * 64 + mi * 16 + qm;
    #pragma unroll
    for (int ni = 0; ni < 8; ni++){
      int c = col0 + wn * 64 + ni * 8 + qk * 2;
      #pragma unroll
      for (int half_ = 0; half_ < 2; half_++){
        int rr = r + half_ * 8;
        float v0 = acc[mi][ni][half_ * 2 + 0];
        float v1 = acc[mi][ni][half_ * 2 + 1];
        if (bias){ if (c < N) v0 += bias[c]; if (c + 1 < N) v1 += bias[c + 1]; }
        if (RELU){ v0 = fmaxf(v0, 0.0f); v1 = fmaxf(v1, 0.0f); }
        if (RESID){
          const float* rp = resid + (size_t)rr * N;
          if (c < N) v0 += rp[c];
          if (c + 1 < N) v1 += rp[c + 1];
        }
        if (OUTH){
          __half* cp = (__half*)C + (size_t)rr * N;
          if (c + 1 < N) *(__half2*)(cp + c) = __floats2half2_rn(v0, v1);
          else if (c < N) cp[c] = __float2half(v0);
        } else {
          float* cp = (float*)C + (size_t)rr * N;
          if (((N & 1) == 0) && c + 1 < N) *(float2*)(cp + c) = make_float2(v0, v1);
          else {
            if (c     < N) cp[c    ] = v0;
            if (c + 1 < N) cp[c + 1] = v1;
          }
        }
      }
    }
  }
}

// ---------------- fused flash attention (causal, fp16 mma16, packed-qkv) ----------------
// grid (T/64, B*H), 128 threads = 4 warps; warp owns 16 q rows.
#define FPH 72                                       // half pitch for Ks/Vs/Ps
#define FLASH_SMEM (3 * 64 * FPH * 2)                // 27648 B

__global__ __launch_bounds__(128)
void flash_attn(const __half* __restrict__ qkv){
  extern __shared__ __align__(16) __half fsm[];
  __half* Ks = fsm;
  __half* Vs = fsm + 64 * FPH;
  __half* Ps = Vs  + 64 * FPH;
  uint32_t KsU = smem_u32(Ks), VsU = smem_u32(Vs), PsU = smem_u32(Ps);

  int it = blockIdx.x, bh = blockIdx.y;
  int b = bh >> 4, hd = bh & 15;
  const __half* qh = qkv + (size_t)b * Tt * QS + hd * Dd;
  const __half* kh = qh + Ee;
  const __half* vh = qh + 2 * Ee;

  int tid = threadIdx.x;
  int lane = tid & 31, warp = tid >> 5;
  int qk = lane & 3, qm = lane >> 2;
  int j8 = lane >> 3, r8 = lane & 7;
  int r0 = warp * 16;

  int aoff = (r0 + ((j8 & 1) << 3) + r8) * FPH + ((j8 >> 1) << 3);
  int koff[4];
  #pragma unroll
  for (int p = 0; p < 4; p++)
    koff[p] = ((p*2 + (j8 >> 1))*8 + r8) * FPH + ((j8 & 1) << 3);
  int voff[4];
  #pragma unroll
  for (int p = 0; p < 4; p++)
    voff[p] = (((j8 & 1) << 3) + r8) * FPH + p*16 + ((j8 >> 1) << 3);

  #pragma unroll
  for (int l = 0; l < 4; l++){
    int f = tid + l * 128;
    int r = f >> 3, c8 = (f & 7) << 3;
    uint4 u = *(const uint4*)(qh + (size_t)(it * 64 + r) * QS + c8);
    *(uint4*)(Ps + r * FPH + c8) = u;
  }
  __syncthreads();
  uint32_t aq[4][4];
  #pragma unroll
  for (int ks = 0; ks < 4; ks++)
    ldsm_x4(aq[ks][0], aq[ks][1], aq[ks][2], aq[ks][3],
            PsU + (uint32_t)(aoff + ks * 16) * 2);

  float oacc[8][4] = {};
  float mold[2] = {-INFINITY, -INFINITY};
  float lrun[2] = {0.0f, 0.0f};
  const float scale = 0.03125f;   // E^{-1/2}

  for (int jt = 0; jt <= it; jt++){
    __syncthreads();
    #pragma unroll
    for (int l = 0; l < 4; l++){
      int f = tid + l * 128;
      int r = f >> 3, c8 = (f & 7) << 3;
      uint4 uk = *(const uint4*)(kh + (size_t)(jt * 64 + r) * QS + c8);
      *(uint4*)(Ks + r * FPH + c8) = uk;
      uint4 uv = *(const uint4*)(vh + (size_t)(jt * 64 + r) * QS + c8);
      *(uint4*)(Vs + r * FPH + c8) = uv;
    }
    __syncthreads();

    float sacc[8][4] = {};
    #pragma unroll
    for (int ks = 0; ks < 4; ks++){
      int k0 = ks * 16;
      uint32_t bf[8][2];
      #pragma unroll
      for (int p = 0; p < 4; p++)
        ldsm_x4(bf[p*2][0], bf[p*2][1], bf[p*2+1][0], bf[p*2+1][1],
                KsU + (uint32_t)(koff[p] + k0) * 2);
      #pragma unroll
      for (int ni = 0; ni < 8; ni++)
        mma16(sacc[ni], aq[ks], bf[ni]);
    }

    bool diag = (jt == it);
    #pragma unroll
    for (int ni = 0; ni < 8; ni++)
      #pragma unroll
      for (int e = 0; e < 4; e++){
        float sv = sacc[ni][e] * scale;
        if (diag){
          int rr = r0 + qm + ((e >> 1) << 3);
          int cc = ni * 8 + (qk << 1) + (e & 1);
          if (cc > rr) sv = -INFINITY;
        }
        sacc[ni][e] = sv;
      }

    #pragma unroll
    for (int h = 0; h < 2; h++){
      float mr = -INFINITY;
      #pragma unroll
      for (int ni = 0; ni < 8; ni++)
        mr = fmaxf(mr, fmaxf(sacc[ni][h * 2], sacc[ni][h * 2 + 1]));
      mr = fmaxf(mr, __shfl_xor_sync(0xffffffffu, mr, 1));
      mr = fmaxf(mr, __shfl_xor_sync(0xffffffffu, mr, 2));
      float mn = fmaxf(mold[h], mr);
      float alpha = __expf(mold[h] - mn);
      mold[h] = mn;
      float ls = 0.0f;
      __half* prow = Ps + (r0 + qm + h * 8) * FPH;
      #pragma unroll
      for (int ni = 0; ni < 8; ni++){
        float p0 = __expf(sacc[ni][h * 2    ] - mn);
        float p1 = __expf(sacc[ni][h * 2 + 1] - mn);
        ls += p0 + p1;
        *(__half2*)(prow + ni * 8 + qk * 2) = __floats2half2_rn(p0, p1);
        oacc[ni][h * 2    ] *= alpha;
        oacc[ni][h * 2 + 1] *= alpha;
      }
      ls += __shfl_xor_sync(0xffffffffu, ls, 1);
      ls += __shfl_xor_sync(0xffffffffu, ls, 2);
      lrun[h] = lrun[h] * alpha + ls;
    }
    __syncwarp();

    #pragma unroll
    for (int ks = 0; ks < 4; ks++){
      int k0 = ks * 16;
      uint32_t ua[4];
      ldsm_x4(ua[0], ua[1], ua[2], ua[3], PsU + (uint32_t)(aoff + k0) * 2);
      uint32_t bf[8][2];
      #pragma unroll
      for (int p = 0; p < 4; p++)
        ldsm_x4_t(bf[p*2][0], bf[p*2][1], bf[p*2+1][0], bf[p*2+1][1],
                  VsU + (uint32_t)(voff[p] + k0 * FPH) * 2);
      #pragma unroll
      for (int ni = 0; ni < 8; ni++)
        mma16(oacc[ni], ua, bf[ni]);
    }
  }

  #pragma unroll
  for (int h = 0; h < 2; h++){
    float inv = 1.0f / lrun[h];
    int gi = it * 64 + r0 + qm + h * 8;
    __half* op = g_oh + (size_t)(b * Tt + gi) * Ee + hd * Dd;
    #pragma unroll
    for (int ni = 0; ni < 8; ni++)
      *(__half2*)(op + ni * 8 + qk * 2) =
          __floats2half2_rn(oacc[ni][h * 2] * inv, oacc[ni][h * 2 + 1] * inv);
  }
}

// ---------------- loss: single-pass online logsumexp ----------------
__global__ void loss_row(const float* __restrict__ logits, const int* __restrict__ tgt){
  int r = blockIdx.x;
  const float* lp = logits + (size_t)r * Vv;
  int tid = threadIdx.x, lane = tid & 31, wid = tid >> 5;
  float m = -INFINITY, s = 0.0f;
  for (int c = tid; c < Vv; c += 256){
    float v = lp[c];
    if (v > m){ s = s * __expf(m - v) + 1.0f; m = v; }
    else s += __expf(v - m);
  }
  #pragma unroll
  for (int o = 16; o > 0; o >>= 1){
    float mo = __shfl_down_sync(0xffffffffu, m, o);
    float so = __shfl_down_sync(0xffffffffu, s, o);
    float mn = fmaxf(m, mo);
    s = s * __expf(m - mn) + so * __expf(mo - mn);
    m = mn;
  }
  __shared__ float shm[8], shs[8];
  if (lane == 0){ shm[wid] = m; shs[wid] = s; }
  __syncthreads();
  if (tid == 0){
    float M = shm[0], S = shs[0];
    #pragma unroll
    for (int i = 1; i < 8; i++){
      float mn = fmaxf(M, shm[i]);
      S = S * __expf(M - mn) + shs[i] * __expf(shm[i] - mn);
      M = mn;
    }
    g_rowloss[r] = -(lp[tgt[r]] - M - logf(S));
  }
}
__global__ void loss_final(float* __restrict__ out){
  float s = 0.0f;
  for (int i = threadIdx.x; i < BT; i += 256) s += g_rowloss[i];
  s = blockReduce<0>(s);
  if (threadIdx.x == 0) out[0] = s / (float)BT;
}

// ---------------- launch ----------------
extern "C" void kernel_launch(void* const* d_in, const int* in_sizes, int n_in,
                              void* d_out, int out_size){
  const int*   idx     = (const int*)  d_in[0];
  const int*   targets = (const int*)  d_in[1];
  const float* tok     = (const float*)d_in[2];
  const float* pos     = (const float*)d_in[3];
  const float* ln1w    = (const float*)d_in[4];
  const float* ln1b    = (const float*)d_in[5];
  const float* Wq      = (const float*)d_in[6];
  const float* Wk      = (const float*)d_in[7];
  const float* Wv      = (const float*)d_in[8];
  const float* projw   = (const float*)d_in[9];
  const float* projb   = (const float*)d_in[10];
  const float* ln2w    = (const float*)d_in[11];
  const float* ln2b    = (const float*)d_in[12];
  const float* fw1     = (const float*)d_in[13];
  const float* fb1     = (const float*)d_in[14];
  const float* fw2     = (const float*)d_in[15];
  const float* fb2     = (const float*)d_in[16];
  const float* lnfw    = (const float*)d_in[17];
  const float* lnfb    = (const float*)d_in[18];
  const float* lmw     = (const float*)d_in[19];
  const float* lmb     = (const float*)d_in[20];

  float  *x, *scratch;
  __half *hh, *qkvh, *oh, *ffh, *wt, *wqkv, *lmwt;
  cudaGetSymbolAddress((void**)&x,    g_x);
  cudaGetSymbolAddress((void**)&hh,   g_hh);
  cudaGetSymbolAddress((void**)&qkvh, g_qkvh);
  cudaGetSymbolAddress((void**)&oh,   g_oh);
  cudaGetSymbolAddress((void**)&ffh,  g_ffh);
  cudaGetSymbolAddress((void**)&wt,   g_wt);
  cudaGetSymbolAddress((void**)&wqkv, g_wqkv);
  cudaGetSymbolAddress((void**)&lmwt, g_lmwt);
  cudaGetSymbolAddress((void**)&scratch, g_logits_scratch);

  cudaFuncSetAttribute(sgemm_hc<false,false,true >, cudaFuncAttributeMaxDynamicSharedMemorySize, SGEMM_SMEM);
  cudaFuncSetAttribute(sgemm_hc<false,true ,false>, cudaFuncAttributeMaxDynamicSharedMemorySize, SGEMM_SMEM);
  cudaFuncSetAttribute(sgemm_hc<true ,false,true >, cudaFuncAttributeMaxDynamicSharedMemorySize, SGEMM_SMEM);
  cudaFuncSetAttribute(sgemm_hc<false,false,false>, cudaFuncAttributeMaxDynamicSharedMemorySize, SGEMM_SMEM);
  cudaFuncSetAttribute(flash_attn, cudaFuncAttributeMaxDynamicSharedMemorySize, FLASH_SMEM);

  const long long bt_v = (long long)BT * Vv;
  float* logits = ((long long)out_size >= bt_v) ? (float*)d_out : scratch;

  embed_kernel<<<BT * Ee / 4 / 256, 256>>>(idx, tok, pos);

  const size_t EE  = (size_t)Ee * Ee;
  const size_t FAM = (size_t)Ll * EE;
  dim3 tb(32, 8), tg(Ee/32, Ee/32, Ll);
  transpose_w<<<tg, tb>>>(Wq,    wqkv + 0*EE, 3*EE);
  transpose_w<<<tg, tb>>>(Wk,    wqkv + 1*EE, 3*EE);
  transpose_w<<<tg, tb>>>(Wv,    wqkv + 2*EE, 3*EE);
  transpose_w<<<tg, tb>>>(projw, wt + 0*FAM, EE);
  transpose_w<<<tg, tb>>>(fw1,   wt + 1*FAM, EE);
  transpose_w<<<tg, tb>>>(fw2,   wt + 2*FAM, EE);
  transpose_lm<<<dim3(Ee/32, NPAD/32), tb>>>(lmw, lmwt);

  dim3 gEE (BT / 128, Ee / 256);        // (32, 4)
  dim3 gQKV(BT / 128, 3 * Ee / 256);    // (32, 12)
  dim3 gAttn(Tt / 64, Bb * Hh);
  for (int l = 0; l < Ll; l++){
    size_t wo = (size_t)l * EE, bo = (size_t)l * Ee;
    ln_kernel<<<BT, 256>>>(x, hh, ln1w + bo, ln1b + bo);
    sgemm_hc<false,false,true ><<<gQKV, 256, SGEMM_SMEM>>>(
        hh, wqkv + (size_t)l * 3 * EE, nullptr, nullptr, qkvh, BT, 3*Ee, Ee, Ee);
    flash_attn<<<gAttn, 128, FLASH_SMEM>>>(qkvh);
    sgemm_hc<false,true ,false><<<gEE, 256, SGEMM_SMEM>>>(oh,  wt + 0*FAM + wo, projb + bo, x, x, BT, Ee, Ee, Ee);
    ln_kernel<<<BT, 256>>>(x, hh, ln2w + bo, ln2b + bo);
    sgemm_hc<true ,false,true ><<<gEE, 256, SGEMM_SMEM>>>(hh,  wt + 1*FAM + wo, fb1 + bo, nullptr, ffh, BT, Ee, Ee, Ee);
    sgemm_hc<false,true ,false><<<gEE, 256, SGEMM_SMEM>>>(ffh, wt + 2*FAM + wo, fb2 + bo, x, x, BT, Ee, Ee, Ee);
  }

  ln_kernel<<<BT, 256>>>(x, hh, lnfw, lnfb);
  sgemm_hc<false,false,false><<<dim3(BT / 128, NPAD / 256), 256, SGEMM_SMEM>>>(
      hh, lmwt, lmb, nullptr, logits, BT, Vv, Ee, Ee);

  if ((long long)out_size != bt_v){
    loss_row<<<BT, 256>>>(logits, targets);
    float* lossptr = ((long long)out_size > bt_v) ? ((float*)d_out) + bt_v
                                                  : (float*)d_out;
    loss_final<<<1, 256>>>(lossptr);
  }
}

// round 12
// speedup vs baseline: 1.1875x; 1.1875x over previous
#include <cuda_runtime.h>
#include <cuda_fp16.h>
#include <math.h>
#include <stdint.h>

#define Bb 4
#define Tt 1024
#define Vv 50257
#define Ee 1024
#define Hh 16
#define Ll 8
#define Dd 64
#define BT (Bb*Tt)
#define NPAD 50304   // Vv padded to multiple of 128
#define NBLK (NPAD/128)   // 393 LM-head column blocks
#define QS  (3*Ee)   // packed qkv row stride

// ---------------- device scratch (static, allocation-free) ----------------
__device__ float  g_x [BT*Ee];                       // fp32 residual stream
__device__ __half g_hh[BT*Ee];                       // LN output (GEMM A)
__device__ __half g_qkvh[(size_t)BT * QS];           // packed q|k|v half
__device__ __half g_oh[BT*Ee];
__device__ __half g_ffh[BT*Ee];
__device__ __half g_wt[(size_t)3 * Ll * Ee * Ee];    // proj/fw1/fw2 transposed [N][K] half
__device__ __half g_wqkv[(size_t)Ll * 3 * Ee * Ee];  // per-layer [3E][E] transposed half
__device__ __half g_lmwt[(size_t)NPAD * Ee];         // LM head transposed [NPAD][Ee] half
__device__ float2 g_lmpart[(size_t)BT * NBLK];       // per (row, colblock) logsumexp partials
__device__ float  g_rowloss[BT];
__device__ float  g_logits_scratch[205852672ull];    // fallback logits buffer

// ---------------- helpers ----------------
__device__ __forceinline__ void mma16(float* c, const uint32_t* a, const uint32_t* b){
  asm volatile("mma.sync.aligned.m16n8k16.row.col.f32.f16.f16.f32 "
    "{%0,%1,%2,%3}, {%4,%5,%6,%7}, {%8,%9}, {%0,%1,%2,%3};"
    : "+f"(c[0]), "+f"(c[1]), "+f"(c[2]), "+f"(c[3])
    : "r"(a[0]), "r"(a[1]), "r"(a[2]), "r"(a[3]), "r"(b[0]), "r"(b[1]));
}
__device__ __forceinline__ void ldsm_x4(uint32_t& r0, uint32_t& r1,
                                        uint32_t& r2, uint32_t& r3, uint32_t addr){
  asm volatile("ldmatrix.sync.aligned.m8n8.x4.shared.b16 {%0,%1,%2,%3}, [%4];"
    : "=r"(r0), "=r"(r1), "=r"(r2), "=r"(r3) : "r"(addr));
}
__device__ __forceinline__ void ldsm_x4_t(uint32_t& r0, uint32_t& r1,
                                          uint32_t& r2, uint32_t& r3, uint32_t addr){
  asm volatile("ldmatrix.sync.aligned.m8n8.x4.trans.shared.b16 {%0,%1,%2,%3}, [%4];"
    : "=r"(r0), "=r"(r1), "=r"(r2), "=r"(r3) : "r"(addr));
}
__device__ __forceinline__ void cp16(void* smem_ptr, const void* g){
  uint32_t s = (uint32_t)__cvta_generic_to_shared(smem_ptr);
  asm volatile("cp.async.cg.shared.global [%0], [%1], 16;" :: "r"(s), "l"(g));
}
__device__ __forceinline__ void cp_commit(){ asm volatile("cp.async.commit_group;"); }
template<int N> __device__ __forceinline__ void cp_wait(){
  asm volatile("cp.async.wait_group %0;" :: "n"(N));
}
__device__ __forceinline__ uint32_t smem_u32(const void* p){
  return (uint32_t)__cvta_generic_to_shared(p);
}
// -INF-safe online logsumexp merge: (M,S) <- (M,S) + (m2,s2)
__device__ __forceinline__ void lse_merge(float& M, float& S, float m2, float s2){
  if (m2 != -INFINITY){
    float Mn = fmaxf(M, m2);
    S = S * __expf(M - Mn) + s2 * __expf(m2 - Mn);
    M = Mn;
  }
}
__device__ __forceinline__ void lse_push(float& M, float& S, float v){
  if (v > M){ S = S * __expf(M - v) + 1.0f; M = v; }
  else S += __expf(v - M);
}

__device__ __forceinline__ float warpSum(float v){
  #pragma unroll
  for (int o = 16; o > 0; o >>= 1) v += __shfl_down_sync(0xffffffffu, v, o);
  return v;
}
__device__ __forceinline__ float warpMax(float v){
  #pragma unroll
  for (int o = 16; o > 0; o >>= 1) v = fmaxf(v, __shfl_down_sync(0xffffffffu, v, o));
  return v;
}
template<int OP>
__device__ __forceinline__ float blockReduce(float v){
  __shared__ float sh[33];
  int lane = threadIdx.x & 31, wid = threadIdx.x >> 5;
  v = OP ? warpMax(v) : warpSum(v);
  __syncthreads();
  if (lane == 0) sh[wid] = v;
  __syncthreads();
  int nw = blockDim.x >> 5;
  if (wid == 0){
    float u = (lane < nw) ? sh[lane] : (OP ? -INFINITY : 0.0f);
    u = OP ? warpMax(u) : warpSum(u);
    if (lane == 0) sh[32] = u;
  }
  __syncthreads();
  return sh[32];
}

// ---------------- embedding (fp32 residual) ----------------
__global__ void embed_kernel(const int* __restrict__ idx,
                             const float* __restrict__ tok,
                             const float* __restrict__ pos){
  int i  = blockIdx.x * 256 + threadIdx.x;
  int e4 = i & (Ee/4 - 1);
  int bt = i >> 8;
  int t  = bt & (Tt - 1);
  int token = idx[bt];
  float4 tv = ((const float4*)(tok + (size_t)token * Ee))[e4];
  float4 pv = ((const float4*)(pos + (size_t)t     * Ee))[e4];
  ((float4*)(g_x + (size_t)bt * Ee))[e4] =
      make_float4(tv.x*pv.x, tv.y*pv.y, tv.z*pv.z, tv.w*pv.w);
}

// ---------------- layernorm: fp32 in -> half out ----------------
__global__ void ln_kernel(const float* __restrict__ in, __half* __restrict__ out,
                          const float* __restrict__ w, const float* __restrict__ b){
  int row = blockIdx.x;
  float4 v = ((const float4*)(in + (size_t)row * Ee))[threadIdx.x];
  float mu = blockReduce<0>(v.x + v.y + v.z + v.w) * (1.0f / Ee);
  float dx = v.x - mu, dy = v.y - mu, dz = v.z - mu, dw = v.w - mu;
  float var = blockReduce<0>(dx*dx + dy*dy + dz*dz + dw*dw) * (1.0f / Ee);
  float rs = rsqrtf(var + 1e-5f);
  float4 wv = ((const float4*)w)[threadIdx.x];
  float4 bv = ((const float4*)b)[threadIdx.x];
  __half2* op = (__half2*)(out + (size_t)row * Ee) + threadIdx.x * 2;
  op[0] = __floats2half2_rn(dx*rs*wv.x + bv.x, dy*rs*wv.y + bv.y);
  op[1] = __floats2half2_rn(dz*rs*wv.z + bv.z, dw*rs*wv.w + bv.w);
}

// ---------------- weight transpose+half: src[K][N] f32 (per layer EE) -> dst[N][K] half
__global__ void transpose_w(const float* __restrict__ src, __half* __restrict__ dst,
                            size_t dstLayerStride){
  __shared__ float t[32][33];
  size_t sbase = (size_t)blockIdx.z * Ee * Ee;
  size_t dbase = (size_t)blockIdx.z * dstLayerStride;
  int k0 = blockIdx.x * 32, n0 = blockIdx.y * 32;
  int tx = threadIdx.x, ty = threadIdx.y;  // 32 x 8
  #pragma unroll
  for (int i = 0; i < 4; i++)
    t[ty + i*8][tx] = src[sbase + (size_t)(k0 + ty + i*8) * Ee + n0 + tx];
  __syncthreads();
  #pragma unroll
  for (int i = 0; i < 4; i++)
    dst[dbase + (size_t)(n0 + ty + i*8) * Ee + k0 + tx] = __float2half(t[tx][ty + i*8]);
}

// LM head: src[Ee][Vv] f32 -> dst[NPAD][Ee] half (zero-padded rows)
__global__ void transpose_lm(const float* __restrict__ src, __half* __restrict__ dst){
  __shared__ float t[32][33];
  int k0 = blockIdx.x * 32, n0 = blockIdx.y * 32;
  int tx = threadIdx.x, ty = threadIdx.y;
  #pragma unroll
  for (int i = 0; i < 4; i++){
    int n = n0 + tx;
    t[ty + i*8][tx] = (n < Vv) ? src[(size_t)(k0 + ty + i*8) * Vv + n] : 0.0f;
  }
  __syncthreads();
  #pragma unroll
  for (int i = 0; i < 4; i++)
    dst[(size_t)(n0 + ty + i*8) * Ee + k0 + tx] = __float2half(t[tx][ty + i*8]);
}

// ---------------- fp16 tensor-core GEMM, BK=64, 2-stage cp.async + ldmatrix ----------------
// C[M,N] = act(A[M,K]@Bt[N,K]^T + bias)(+resid). BM=BN=128, BK=64, mma m16n8k16.
// LOGIT: also emit per-(row, colblock) online-logsumexp partials to g_lmpart.
#define HPITCH 72                        // halfs per smem row (36 words: 4r mod 32 distinct)
#define TILEH  (128*HPITCH)              // 9216 halfs per operand tile
#define STAGEH (2*TILEH)                 // 18432 halfs per stage
#define SGEMM_SMEM (2*STAGEH*2)          // 73728 bytes (2 stages)

template<bool RELU, bool RESID, bool OUTH, bool LOGIT>
__global__ __launch_bounds__(256, 2)
void sgemm_hc(const __half* __restrict__ A, const __half* __restrict__ Bt,
              const float* __restrict__ bias, const float* __restrict__ resid,
              void* __restrict__ C, int M, int N, int K, int Kb){
  extern __shared__ __align__(16) __half hsm[];
  int tid = threadIdx.x;
  int lane = tid & 31, warp = tid >> 5;
  int wm = warp >> 2, wn = warp & 3;
  int qk = lane & 3, qm = lane >> 2;
  int row0 = blockIdx.x * 128, col0 = blockIdx.y * 128;
  float acc[4][4][4] = {};

  // per-lane ldmatrix offsets (in half units)
  int j8 = lane >> 3, r8 = lane & 7;
  int a_off[4], b_off[2];
  #pragma unroll
  for (int mi = 0; mi < 4; mi++)
    a_off[mi] = (wm*64 + mi*16 + ((j8 & 1) << 3) + r8) * HPITCH + ((j8 >> 1) << 3);
  #pragma unroll
  for (int p = 0; p < 2; p++)
    b_off[p] = (wn*32 + (p*2 + (j8 >> 1))*8 + r8) * HPITCH + ((j8 & 1) << 3);

  auto prefetch = [&](int kt, int s){
    __half* As = hsm + s * STAGEH;
    __half* Bs = As + TILEH;
    #pragma unroll
    for (int l = 0; l < 4; l++){
      int f = tid + l * 256;                 // 1024 chunks: 128 rows x 8 x 16B
      int r = f >> 3, c8 = (f & 7) << 3;
      cp16(As + r * HPITCH + c8, A  + (size_t)(row0 + r) * K  + kt + c8);
    }
    #pragma unroll
    for (int l = 0; l < 4; l++){
      int f = tid + l * 256;
      int r = f >> 3, c8 = (f & 7) << 3;
      cp16(Bs + r * HPITCH + c8, Bt + (size_t)(col0 + r) * Kb + kt + c8);
    }
  };

  int nk = K >> 6;                            // 64-half K chunks
  prefetch(0, 0); cp_commit();

  for (int t = 0; t < nk; t++){
    cp_wait<0>();
    __syncthreads();     // publishes stage t&1; orders prior reads of (t+1)&1 vs prefetch
    if (t + 1 < nk){ prefetch((t + 1) << 6, (t + 1) & 1); cp_commit(); }
    uint32_t aU = smem_u32(hsm + (t & 1) * STAGEH);
    uint32_t bU = aU + TILEH * 2;
    #pragma unroll
    for (int ks = 0; ks < 4; ks++){
      int k0 = ks * 16;
      uint32_t af[4][4], bf[4][2];
      #pragma unroll
      for (int mi = 0; mi < 4; mi++)
        ldsm_x4(af[mi][0], af[mi][1], af[mi][2], af[mi][3],
                aU + (uint32_t)(a_off[mi] + k0) * 2);
      #pragma unroll
      for (int p = 0; p < 2; p++)
        ldsm_x4(bf[p*2][0], bf[p*2][1], bf[p*2+1][0], bf[p*2+1][1],
                bU + (uint32_t)(b_off[p] + k0) * 2);
      #pragma unroll
      for (int mi = 0; mi < 4; mi++)
        #pragma unroll
        for (int ni = 0; ni < 4; ni++)
          mma16(acc[mi][ni], af[mi], bf[ni]);
    }
  }

  float pm[4][2], ps[4][2];
  if (LOGIT){
    #pragma unroll
    for (int mi = 0; mi < 4; mi++){ pm[mi][0]=pm[mi][1]=-INFINITY; ps[mi][0]=ps[mi][1]=0.0f; }
  }

  #pragma unroll
  for (int mi = 0; mi < 4; mi++){
    int r = row0 + wm * 64 + mi * 16 + qm;
    #pragma unroll
    for (int ni = 0; ni < 4; ni++){
      int c = col0 + wn * 32 + ni * 8 + qk * 2;
      #pragma unroll
      for (int half_ = 0; half_ < 2; half_++){
        int rr = r + half_ * 8;
        float v0 = acc[mi][ni][half_ * 2 + 0];
        float v1 = acc[mi][ni][half_ * 2 + 1];
        if (bias){ if (c < N) v0 += bias[c]; if (c + 1 < N) v1 += bias[c + 1]; }
        if (RELU){ v0 = fmaxf(v0, 0.0f); v1 = fmaxf(v1, 0.0f); }
        if (RESID){
          const float* rp = resid + (size_t)rr * N;
          if (c < N) v0 += rp[c];
          if (c + 1 < N) v1 += rp[c + 1];
        }
        if (LOGIT){
          if (c     < N) lse_push(pm[mi][half_], ps[mi][half_], v0);
          if (c + 1 < N) lse_push(pm[mi][half_], ps[mi][half_], v1);
        }
        if (OUTH){
          __half* cp = (__half*)C + (size_t)rr * N;
          if (c + 1 < N) *(__half2*)(cp + c) = __floats2half2_rn(v0, v1);
          else if (c < N) cp[c] = __float2half(v0);
        } else {
          float* cp = (float*)C + (size_t)rr * N;
          if (((N & 1) == 0) && c + 1 < N) *(float2*)(cp + c) = make_float2(v0, v1);
          else {
            if (c     < N) cp[c    ] = v0;
            if (c + 1 < N) cp[c + 1] = v1;
          }
        }
      }
    }
  }

  if (LOGIT){
    // reduce over the 4 qk lanes sharing each row (lane xor 1, xor 2)
    #pragma unroll
    for (int mi = 0; mi < 4; mi++)
      #pragma unroll
      for (int h = 0; h < 2; h++){
        #pragma unroll
        for (int o = 1; o <= 2; o <<= 1){
          float mo = __shfl_xor_sync(0xffffffffu, pm[mi][h], o);
          float so = __shfl_xor_sync(0xffffffffu, ps[mi][h], o);
          lse_merge(pm[mi][h], ps[mi][h], mo, so);
        }
      }
    __syncthreads();                 // mainloop smem reads all done; reuse hsm
    float* pmS = (float*)hsm;        // [128 rows][4 wn]
    float* psS = pmS + 128 * 4;
    if (qk == 0){
      #pragma unroll
      for (int mi = 0; mi < 4; mi++)
        #pragma unroll
        for (int h = 0; h < 2; h++){
          int lr = wm * 64 + mi * 16 + qm + h * 8;
          pmS[lr * 4 + wn] = pm[mi][h];
          psS[lr * 4 + wn] = ps[mi][h];
        }
    }
    __syncthreads();
    if (tid < 128){
      float M = -INFINITY, S = 0.0f;
      #pragma unroll
      for (int w = 0; w < 4; w++)
        lse_merge(M, S, pmS[tid * 4 + w], psS[tid * 4 + w]);
      g_lmpart[(size_t)(row0 + tid) * NBLK + blockIdx.y] = make_float2(M, S);
    }
  }
}

// ---------------- fused flash attention (causal, fp16 mma16, packed-qkv) ----------------
// grid (T/64, B*H), 128 threads = 4 warps; warp owns 16 q rows.
#define FPH 72                                       // half pitch for Ks/Vs/Ps
#define FLASH_SMEM (3 * 64 * FPH * 2)                // 27648 B

__global__ __launch_bounds__(128)
void flash_attn(const __half* __restrict__ qkv){
  extern __shared__ __align__(16) __half fsm[];
  __half* Ks = fsm;
  __half* Vs = fsm + 64 * FPH;
  __half* Ps = Vs  + 64 * FPH;
  uint32_t KsU = smem_u32(Ks), VsU = smem_u32(Vs), PsU = smem_u32(Ps);

  int it = blockIdx.x, bh = blockIdx.y;
  int b = bh >> 4, hd = bh & 15;
  const __half* qh = qkv + (size_t)b * Tt * QS + hd * Dd;
  const __half* kh = qh + Ee;
  const __half* vh = qh + 2 * Ee;

  int tid = threadIdx.x;
  int lane = tid & 31, warp = tid >> 5;
  int qk = lane & 3, qm = lane >> 2;
  int j8 = lane >> 3, r8 = lane & 7;
  int r0 = warp * 16;

  int aoff = (r0 + ((j8 & 1) << 3) + r8) * FPH + ((j8 >> 1) << 3);
  int koff[4];
  #pragma unroll
  for (int p = 0; p < 4; p++)
    koff[p] = ((p*2 + (j8 >> 1))*8 + r8) * FPH + ((j8 & 1) << 3);
  int voff[4];
  #pragma unroll
  for (int p = 0; p < 4; p++)
    voff[p] = (((j8 & 1) << 3) + r8) * FPH + p*16 + ((j8 >> 1) << 3);

  #pragma unroll
  for (int l = 0; l < 4; l++){
    int f = tid + l * 128;
    int r = f >> 3, c8 = (f & 7) << 3;
    uint4 u = *(const uint4*)(qh + (size_t)(it * 64 + r) * QS + c8);
    *(uint4*)(Ps + r * FPH + c8) = u;
  }
  __syncthreads();
  uint32_t aq[4][4];
  #pragma unroll
  for (int ks = 0; ks < 4; ks++)
    ldsm_x4(aq[ks][0], aq[ks][1], aq[ks][2], aq[ks][3],
            PsU + (uint32_t)(aoff + ks * 16) * 2);

  float oacc[8][4] = {};
  float mold[2] = {-INFINITY, -INFINITY};
  float lrun[2] = {0.0f, 0.0f};
  const float scale = 0.03125f;   // E^{-1/2}

  for (int jt = 0; jt <= it; jt++){
    __syncthreads();
    #pragma unroll
    for (int l = 0; l < 4; l++){
      int f = tid + l * 128;
      int r = f >> 3, c8 = (f & 7) << 3;
      uint4 uk = *(const uint4*)(kh + (size_t)(jt * 64 + r) * QS + c8);
      *(uint4*)(Ks + r * FPH + c8) = uk;
      uint4 uv = *(const uint4*)(vh + (size_t)(jt * 64 + r) * QS + c8);
      *(uint4*)(Vs + r * FPH + c8) = uv;
    }
    __syncthreads();

    float sacc[8][4] = {};
    #pragma unroll
    for (int ks = 0; ks < 4; ks++){
      int k0 = ks * 16;
      uint32_t bf[8][2];
      #pragma unroll
      for (int p = 0; p < 4; p++)
        ldsm_x4(bf[p*2][0], bf[p*2][1], bf[p*2+1][0], bf[p*2+1][1],
                KsU + (uint32_t)(koff[p] + k0) * 2);
      #pragma unroll
      for (int ni = 0; ni < 8; ni++)
        mma16(sacc[ni], aq[ks], bf[ni]);
    }

    bool diag = (jt == it);
    #pragma unroll
    for (int ni = 0; ni < 8; ni++)
      #pragma unroll
      for (int e = 0; e < 4; e++){
        float sv = sacc[ni][e] * scale;
        if (diag){
          int rr = r0 + qm + ((e >> 1) << 3);
          int cc = ni * 8 + (qk << 1) + (e & 1);
          if (cc > rr) sv = -INFINITY;
        }
        sacc[ni][e] = sv;
      }

    #pragma unroll
    for (int h = 0; h < 2; h++){
      float mr = -INFINITY;
      #pragma unroll
      for (int ni = 0; ni < 8; ni++)
        mr = fmaxf(mr, fmaxf(sacc[ni][h * 2], sacc[ni][h * 2 + 1]));
      mr = fmaxf(mr, __shfl_xor_sync(0xffffffffu, mr, 1));
      mr = fmaxf(mr, __shfl_xor_sync(0xffffffffu, mr, 2));
      float mn = fmaxf(mold[h], mr);
      float alpha = __expf(mold[h] - mn);
      mold[h] = mn;
      float ls = 0.0f;
      __half* prow = Ps + (r0 + qm + h * 8) * FPH;
      #pragma unroll
      for (int ni = 0; ni < 8; ni++){
        float p0 = __expf(sacc[ni][h * 2    ] - mn);
        float p1 = __expf(sacc[ni][h * 2 + 1] - mn);
        ls += p0 + p1;
        *(__half2*)(prow + ni * 8 + qk * 2) = __floats2half2_rn(p0, p1);
        oacc[ni][h * 2    ] *= alpha;
        oacc[ni][h * 2 + 1] *= alpha;
      }
      ls += __shfl_xor_sync(0xffffffffu, ls, 1);
      ls += __shfl_xor_sync(0xffffffffu, ls, 2);
      lrun[h] = lrun[h] * alpha + ls;
    }
    __syncwarp();

    #pragma unroll
    for (int ks = 0; ks < 4; ks++){
      int k0 = ks * 16;
      uint32_t ua[4];
      ldsm_x4(ua[0], ua[1], ua[2], ua[3], PsU + (uint32_t)(aoff + k0) * 2);
      uint32_t bf[8][2];
      #pragma unroll
      for (int p = 0; p < 4; p++)
        ldsm_x4_t(bf[p*2][0], bf[p*2][1], bf[p*2+1][0], bf[p*2+1][1],
                  VsU + (uint32_t)(voff[p] + k0 * FPH) * 2);
      #pragma unroll
      for (int ni = 0; ni < 8; ni++)
        mma16(oacc[ni], ua, bf[ni]);
    }
  }

  #pragma unroll
  for (int h = 0; h < 2; h++){
    float inv = 1.0f / lrun[h];
    int gi = it * 64 + r0 + qm + h * 8;
    __half* op = g_oh + (size_t)(b * Tt + gi) * Ee + hd * Dd;
    #pragma unroll
    for (int ni = 0; ni < 8; ni++)
      *(__half2*)(op + ni * 8 + qk * 2) =
          __floats2half2_rn(oacc[ni][h * 2] * inv, oacc[ni][h * 2 + 1] * inv);
  }
}

// ---------------- loss from LM-head partials ----------------
__global__ void loss_parts(const float* __restrict__ logits, const int* __restrict__ tgt){
  int r = blockIdx.x;
  int tid = threadIdx.x, lane = tid & 31, wid = tid >> 5;   // 128 threads
  float M = -INFINITY, S = 0.0f;
  for (int i = tid; i < NBLK; i += 128){
    float2 p = g_lmpart[(size_t)r * NBLK + i];
    lse_merge(M, S, p.x, p.y);
  }
  #pragma unroll
  for (int o = 16; o > 0; o >>= 1){
    float mo = __shfl_down_sync(0xffffffffu, M, o);
    float so = __shfl_down_sync(0xffffffffu, S, o);
    lse_merge(M, S, mo, so);
  }
  __shared__ float shm[4], shs[4];
  if (lane == 0){ shm[wid] = M; shs[wid] = S; }
  __syncthreads();
  if (tid == 0){
    #pragma unroll
    for (int i = 1; i < 4; i++) lse_merge(shm[0], shs[0], shm[i], shs[i]);
    g_rowloss[r] = -(logits[(size_t)r * Vv + tgt[r]] - shm[0] - logf(shs[0]));
  }
}
__global__ void loss_final(float* __restrict__ out){
  float s = 0.0f;
  for (int i = threadIdx.x; i < BT; i += 256) s += g_rowloss[i];
  s = blockReduce<0>(s);
  if (threadIdx.x == 0) out[0] = s / (float)BT;
}

// ---------------- launch ----------------
extern "C" void kernel_launch(void* const* d_in, const int* in_sizes, int n_in,
                              void* d_out, int out_size){
  const int*   idx     = (const int*)  d_in[0];
  const int*   targets = (const int*)  d_in[1];
  const float* tok     = (const float*)d_in[2];
  const float* pos     = (const float*)d_in[3];
  const float* ln1w    = (const float*)d_in[4];
  const float* ln1b    = (const float*)d_in[5];
  const float* Wq      = (const float*)d_in[6];
  const float* Wk      = (const float*)d_in[7];
  const float* Wv      = (const float*)d_in[8];
  const float* projw   = (const float*)d_in[9];
  const float* projb   = (const float*)d_in[10];
  const float* ln2w    = (const float*)d_in[11];
  const float* ln2b    = (const float*)d_in[12];
  const float* fw1     = (const float*)d_in[13];
  const float* fb1     = (const float*)d_in[14];
  const float* fw2     = (const float*)d_in[15];
  const float* fb2     = (const float*)d_in[16];
  const float* lnfw    = (const float*)d_in[17];
  const float* lnfb    = (const float*)d_in[18];
  const float* lmw     = (const float*)d_in[19];
  const float* lmb     = (const float*)d_in[20];

  float  *x, *scratch;
  __half *hh, *qkvh, *oh, *ffh, *wt, *wqkv, *lmwt;
  cudaGetSymbolAddress((void**)&x,    g_x);
  cudaGetSymbolAddress((void**)&hh,   g_hh);
  cudaGetSymbolAddress((void**)&qkvh, g_qkvh);
  cudaGetSymbolAddress((void**)&oh,   g_oh);
  cudaGetSymbolAddress((void**)&ffh,  g_ffh);
  cudaGetSymbolAddress((void**)&wt,   g_wt);
  cudaGetSymbolAddress((void**)&wqkv, g_wqkv);
  cudaGetSymbolAddress((void**)&lmwt, g_lmwt);
  cudaGetSymbolAddress((void**)&scratch, g_logits_scratch);

  cudaFuncSetAttribute(sgemm_hc<false,false,true ,false>, cudaFuncAttributeMaxDynamicSharedMemorySize, SGEMM_SMEM);
  cudaFuncSetAttribute(sgemm_hc<false,true ,false,false>, cudaFuncAttributeMaxDynamicSharedMemorySize, SGEMM_SMEM);
  cudaFuncSetAttribute(sgemm_hc<true ,false,true ,false>, cudaFuncAttributeMaxDynamicSharedMemorySize, SGEMM_SMEM);
  cudaFuncSetAttribute(sgemm_hc<false,false,false,true >, cudaFuncAttributeMaxDynamicSharedMemorySize, SGEMM_SMEM);
  cudaFuncSetAttribute(flash_attn, cudaFuncAttributeMaxDynamicSharedMemorySize, FLASH_SMEM);

  const long long bt_v = (long long)BT * Vv;
  float* logits = ((long long)out_size >= bt_v) ? (float*)d_out : scratch;

  embed_kernel<<<BT * Ee / 4 / 256, 256>>>(idx, tok, pos);

  const size_t EE  = (size_t)Ee * Ee;
  const size_t FAM = (size_t)Ll * EE;
  dim3 tb(32, 8), tg(Ee/32, Ee/32, Ll);
  transpose_w<<<tg, tb>>>(Wq,    wqkv + 0*EE, 3*EE);
  transpose_w<<<tg, tb>>>(Wk,    wqkv + 1*EE, 3*EE);
  transpose_w<<<tg, tb>>>(Wv,    wqkv + 2*EE, 3*EE);
  transpose_w<<<tg, tb>>>(projw, wt + 0*FAM, EE);
  transpose_w<<<tg, tb>>>(fw1,   wt + 1*FAM, EE);
  transpose_w<<<tg, tb>>>(fw2,   wt + 2*FAM, EE);
  transpose_lm<<<dim3(Ee/32, NPAD/32), tb>>>(lmw, lmwt);

  dim3 gEE (BT / 128, Ee / 128);        // (32, 8)
  dim3 gQKV(BT / 128, 3 * Ee / 128);    // (32, 24)
  dim3 gAttn(Tt / 64, Bb * Hh);
  for (int l = 0; l < Ll; l++){
    size_t wo = (size_t)l * EE, bo = (size_t)l * Ee;
    ln_kernel<<<BT, 256>>>(x, hh, ln1w + bo, ln1b + bo);
    sgemm_hc<false,false,true ,false><<<gQKV, 256, SGEMM_SMEM>>>(
        hh, wqkv + (size_t)l * 3 * EE, nullptr, nullptr, qkvh, BT, 3*Ee, Ee, Ee);
    flash_attn<<<gAttn, 128, FLASH_SMEM>>>(qkvh);
    sgemm_hc<false,true ,false,false><<<gEE, 256, SGEMM_SMEM>>>(oh,  wt + 0*FAM + wo, projb + bo, x, x, BT, Ee, Ee, Ee);
    ln_kernel<<<BT, 256>>>(x, hh, ln2w + bo, ln2b + bo);
    sgemm_hc<true ,false,true ,false><<<gEE, 256, SGEMM_SMEM>>>(hh,  wt + 1*FAM + wo, fb1 + bo, nullptr, ffh, BT, Ee, Ee, Ee);
    sgemm_hc<false,true ,false,false><<<gEE, 256, SGEMM_SMEM>>>(ffh, wt + 2*FAM + wo, fb2 + bo, x, x, BT, Ee, Ee, Ee);
  }

  ln_kernel<<<BT, 256>>>(x, hh, lnfw, lnfb);
  sgemm_hc<false,false,false,true ><<<dim3(BT / 128, NBLK), 256, SGEMM_SMEM>>>(
      hh, lmwt, lmb, nullptr, logits, BT, Vv, Ee, Ee);

  if ((long long)out_size != bt_v){
    loss_parts<<<BT, 128>>>(logits, targets);
    float* lossptr = ((long long)out_size > bt_v) ? ((float*)d_out) + bt_v
                                                  : (float*)d_out;
    loss_final<<<1, 256>>>(lossptr);
  }
}